// round 8
// baseline (speedup 1.0000x reference)
#include <cuda_runtime.h>
#include <cstdint>
#include <math.h>

#define BB 128
#define SS 2048
#define TTAGS 64

__device__ float g_part[BB];
__device__ float g_score[BB];

// 0 -> 1-byte mask elements (uint8/bool), 1 -> 4-byte (int32/float32).
__device__ __forceinline__ int mask_mode_of(const void* m)
{
    uint32_t w0 = *(const uint32_t*)m;
    if (w0 == 0x01010101u) return 0;
    if (w0 == 0x3F800000u) return 1;
    if ((w0 >> 8) == 0u)   return 1;
    return 0;
}

// Default HW barrier (all 160 block threads) — floor ~7cyc vs ~47 for named.
#define PART_BAR() asm volatile("bar.sync 0;" ::: "memory")

// ---------------------------------------------------------------------------
// One kernel, grid = 256 blocks x 160 threads:
//   blocks 0..127   : partition for batch b (warps 0-3 consumers + warp 4
//                     producer). All 160 threads join every bar.sync 0.
//   blocks 128..255 : gold-path score for batch b-128 (warp 0 only; other
//                     warps exit immediately; no barriers on this path).
// Consumers: split-K x2 — lane pair (l, l+16) of warp w owns state
// j = w*16 + (l&15); half h = l>>4 does the 32-term half-dot, combined by
// shfl_xor(16). Producer streams emissions into a 16-deep ring of
// F_t[j] = exp(em+c_j), 15 rounds ahead, joining the same barrier.
// Linear space: q'(j) = (sum_i q(i)*exp(T[i][j]-c_j)) * F_t(j);
// exact pow2 renorm every 4 steps via exponent(q_prev[0]).
// ---------------------------------------------------------------------------
__global__ void __launch_bounds__(160, 1) crf_part_score_kernel(
    const float* __restrict__ em,
    const int* __restrict__ tags,
    const void* __restrict__ maskv,
    const float* __restrict__ trans,
    const float* __restrict__ startt,
    const float* __restrict__ endt)
{
    const int t = threadIdx.x;
    const int mmode = mask_mode_of(maskv);

    // ================= score blocks (blockIdx 128..255) =================
    if (blockIdx.x >= BB) {
        if (t >= 32) return;          // warp 0 only; no barriers below
        const int b = blockIdx.x - BB;
        const int lane = t;
        const int* tg = tags + (size_t)b * SS;
        const float* emb = em + (size_t)b * SS * TTAGS;
        const unsigned char* mb8 = (const unsigned char*)maskv + (size_t)b * SS;
        const uint32_t* mb32 = (const uint32_t*)maskv + (size_t)b * SS;

        float s = 0.f;
        int cnt = 0;
        for (int i = lane; i < SS; i += 32) {
            int tc = tg[i];
            int m = (mmode == 0) ? (mb8[i] != 0) : (mb32[i] != 0u);
            cnt += m;
            if (i == 0) {
                s += startt[tc] + emb[tc];
            } else if (m) {
                s += trans[tc * TTAGS + tg[i - 1]] + emb[(size_t)i * TTAGS + tc];
            }
        }
        #pragma unroll
        for (int o = 16; o > 0; o >>= 1) {
            s += __shfl_xor_sync(0xffffffffu, s, o);
            cnt += __shfl_xor_sync(0xffffffffu, cnt, o);
        }
        if (lane == 0) {
            int last = cnt > 0 ? cnt - 1 : 0;
            g_score[b] = s + endt[tg[last]];
        }
        return;
    }

    // ================= partition blocks (blockIdx 0..127) =================
    __shared__ __align__(16) float qs0[68];
    __shared__ __align__(16) float qs1[68];
    __shared__ __align__(16) float ringF[16][TTAGS];   // 4KB F ring
    __shared__ float wred[4];
    __shared__ unsigned char msk[SS];

    const int b = blockIdx.x;

    // ---------------- producer warp (threads 128..159) ----------------
    if (t >= 128) {
        const int p = t - 128;           // 0..31, owns states 2p, 2p+1
        const int j0 = 2 * p;

        float c0 = -3.0e38f, c1 = -3.0e38f;
        #pragma unroll
        for (int i = 0; i < TTAGS; i++) {
            c0 = fmaxf(c0, trans[i * TTAGS + j0]);
            c1 = fmaxf(c1, trans[i * TTAGS + j0 + 1]);
        }

        const float2* embp =
            (const float2*)(em + (size_t)b * SS * TTAGS + j0);  // [t] -> pair

        // prefill F(1..15) synchronously
        #pragma unroll
        for (int u = 1; u < 16; u++) {
            float2 r = embp[(size_t)u * (TTAGS / 2)];
            *(float2*)&ringF[u][j0] =
                make_float2(__expf(r.x + c0), __expf(r.y + c1));
        }

#define P_LOADR(BUF, U0)                                                         \
        do {                                                                     \
            _Pragma("unroll")                                                    \
            for (int g = 0; g < 8; g++) {                                        \
                int u = (U0) + g;                                                \
                int uc = u < SS ? u : (SS - 1);                                  \
                BUF[g] = embp[(size_t)uc * (TTAGS / 2)];                         \
            }                                                                    \
        } while (0)

        float2 rA[8], rB[8];
        P_LOADR(rA, 16);     // raws for steps 16..23
        P_LOADR(rB, 24);     // raws for steps 24..31
        PART_BAR();          // init barrier (matches consumers)

        // rounds t = 1+it*16+k; at round t produce F(t+15)
        #pragma unroll 1
        for (int it = 0; it < 128; it++) {
            const int rbase = 1 + it * 16;   // first round of this group
            const int pbase = rbase + 15;    // first produced step
            #pragma unroll
            for (int k = 0; k < 8; k++) {
                int rt = rbase + k;
                int u  = pbase + k;          // slot = (pbase+k)&15 = k
                if (rt < SS) {
                    if (u < SS)
                        *(float2*)&ringF[k][j0] =
                            make_float2(__expf(rA[k].x + c0), __expf(rA[k].y + c1));
                    PART_BAR();
                }
            }
            P_LOADR(rA, pbase + 16);
            #pragma unroll
            for (int k = 0; k < 8; k++) {
                int rt = rbase + 8 + k;
                int u  = pbase + 8 + k;      // slot = 8+k
                if (rt < SS) {
                    if (u < SS)
                        *(float2*)&ringF[8 + k][j0] =
                            make_float2(__expf(rB[k].x + c0), __expf(rB[k].y + c1));
                    PART_BAR();
                }
            }
            P_LOADR(rB, pbase + 24);
        }
        PART_BAR();          // matches consumers' final reduce barrier
        return;
#undef P_LOADR
    }

    // ---------------- consumer warps (threads 0..127) ----------------
    const int w = t >> 5;
    const int l = t & 31;
    const int j = w * 16 + (l & 15);        // state owned by this lane pair
    const int h = l >> 4;                   // dot-product half
    const int sidx = j + ((j >> 5) << 2);   // padded q index
    const uint32_t hoff = (uint32_t)h * 144;

    // ---- stage mask row into shared as bytes ----
    if (mmode == 0) {
        const uint32_t* m32 =
            (const uint32_t*)((const unsigned char*)maskv + (size_t)b * SS);
        uint32_t* s32 = (uint32_t*)msk;
        #pragma unroll
        for (int i = 0; i < (SS / 4) / 128; i++)
            s32[t + i * 128] = m32[t + i * 128];
    } else {
        const uint32_t* m32 = (const uint32_t*)maskv + (size_t)b * SS;
        #pragma unroll
        for (int i = 0; i < SS / 128; i++)
            msk[t + i * 128] = (m32[t + i * 128] != 0u) ? 1 : 0;
    }

    // ---- column max c_j (same scan order as producer -> bitwise equal) ----
    float c = -3.0e38f;
    #pragma unroll
    for (int i = 0; i < TTAGS; i++) c = fmaxf(c, trans[i * TTAGS + j]);

    // ---- Ê half-column: i in [h*32, h*32+32), packed f32x2 pairs ----
    unsigned long long epk[16];
    #pragma unroll
    for (int k = 0; k < 16; k++) {
        int i0 = h * 32 + 2 * k;
        float e0 = __expf(trans[i0 * TTAGS + j] - c);
        float e1 = __expf(trans[(i0 + 1) * TTAGS + j] - c);
        epk[k] = (unsigned long long)__float_as_uint(e0) |
                 ((unsigned long long)__float_as_uint(e1) << 32);
    }

    // alpha0 (both halves compute; h==0 stores)
    float qreg = __expf(startt[j] + em[(size_t)b * SS * TTAGS + j]);
    if (h == 0) qs0[sidx] = qreg;
    int esum = 0;
    PART_BAR();   // init barrier

    // ---- one forward step; SL = compile-time ring slot ----
#define CRF_STEP(QSRC, QDST, TTI, SL, DOREN)                                     \
    do {                                                                         \
        int mv = msk[(TTI)];                                                     \
        float Fv = ringF[(SL)][j];                                               \
        uint32_t q0w = 0;                                                        \
        if (DOREN) q0w = *(const uint32_t*)(QSRC);                               \
        const ulonglong2* qv =                                                   \
            (const ulonglong2*)((const char*)(QSRC) + hoff);                     \
        unsigned long long a0 = 0ull, a1 = 0ull, a2 = 0ull, a3 = 0ull;           \
        _Pragma("unroll")                                                        \
        for (int k2 = 0; k2 < 4; k2++) {                                         \
            ulonglong2 v0 = qv[2 * k2];                                          \
            ulonglong2 v1 = qv[2 * k2 + 1];                                      \
            asm("fma.rn.f32x2 %0, %1, %2, %0;" : "+l"(a0) : "l"(v0.x), "l"(epk[4*k2+0])); \
            asm("fma.rn.f32x2 %0, %1, %2, %0;" : "+l"(a1) : "l"(v0.y), "l"(epk[4*k2+1])); \
            asm("fma.rn.f32x2 %0, %1, %2, %0;" : "+l"(a2) : "l"(v1.x), "l"(epk[4*k2+2])); \
            asm("fma.rn.f32x2 %0, %1, %2, %0;" : "+l"(a3) : "l"(v1.y), "l"(epk[4*k2+3])); \
        }                                                                        \
        asm("add.rn.f32x2 %0, %0, %1;" : "+l"(a0) : "l"(a1));                    \
        asm("add.rn.f32x2 %0, %0, %1;" : "+l"(a2) : "l"(a3));                    \
        asm("add.rn.f32x2 %0, %0, %1;" : "+l"(a0) : "l"(a2));                    \
        float accf = __uint_as_float((uint32_t)a0) +                             \
                     __uint_as_float((uint32_t)(a0 >> 32));                      \
        float tot = accf + __shfl_xor_sync(0xffffffffu, accf, 16);               \
        float tj = tot * Fv;                                                     \
        float qn = mv ? tj : qreg;                                               \
        if (DOREN) {                                                             \
            int e = (int)((q0w >> 23) & 0xffu) - 127;                            \
            qn *= __int_as_float((127 - e) << 23);                               \
            esum += e;                                                           \
        }                                                                        \
        qreg = qn;                                                               \
        if (h == 0) (QDST)[sidx] = qn;                                           \
        PART_BAR();                                                              \
    } while (0)

    // steps t = 1 .. 2047 (t = 2048 guarded off). Slot of step (1+it*16+gg)
    // is (1+gg)&15 — compile-time. Parity alternates qs0/qs1 by gg.
    #pragma unroll 1
    for (int it = 0; it < 128; it++) {
        const int base = 1 + it * 16;
        #pragma unroll
        for (int gg = 0; gg < 16; gg += 2) {
            int t0 = base + gg;
            if (t0 < SS) { CRF_STEP(qs0, qs1, t0, (1 + gg) & 15, ((gg & 3) == 0)); }
            int t1 = base + gg + 1;
            if (t1 < SS) { CRF_STEP(qs1, qs0, t1, (2 + gg) & 15, 0); }
        }
    }

    // logZ = log(sum_j q_j * exp(end_j)) + esum*ln2
    float v = (h == 0) ? qreg * __expf(endt[j]) : 0.f;
    #pragma unroll
    for (int o = 16; o > 0; o >>= 1)
        v += __shfl_xor_sync(0xffffffffu, v, o);
    if (l == 0) wred[w] = v;
    PART_BAR();   // final barrier (matched by producer)
    if (t == 0)
        g_part[b] = (float)(log((double)(wred[0] + wred[1] + wred[2] + wred[3])) +
                            (double)esum * 0.6931471805599453);

#undef CRF_STEP
}

// ---------------------------------------------------------------------------
// out = mean(partition - score)
// ---------------------------------------------------------------------------
__global__ void crf_final_kernel(float* __restrict__ out)
{
    const int i = threadIdx.x;  // 128 threads
    double v = (double)g_part[i] - (double)g_score[i];
    #pragma unroll
    for (int o = 16; o > 0; o >>= 1)
        v += __shfl_xor_sync(0xffffffffu, v, o);
    __shared__ double sm[4];
    if ((i & 31) == 0) sm[i >> 5] = v;
    __syncthreads();
    if (i == 0)
        out[0] = (float)((sm[0] + sm[1] + sm[2] + sm[3]) * (1.0 / (double)BB));
}

extern "C" void kernel_launch(void* const* d_in, const int* in_sizes, int n_in,
                              void* d_out, int out_size)
{
    const float* em     = (const float*)d_in[0];
    const int* tags     = (const int*)d_in[1];
    const void* mask    = (const void*)d_in[2];
    const float* trans  = (const float*)d_in[3];
    const float* startt = (const float*)d_in[4];
    const float* endt   = (const float*)d_in[5];

    crf_part_score_kernel<<<2 * BB, 160>>>(em, tags, mask, trans, startt, endt);
    crf_final_kernel<<<1, 128>>>((float*)d_out);
}

// round 10
// speedup vs baseline: 1.3398x; 1.3398x over previous
#include <cuda_runtime.h>
#include <cstdint>
#include <math.h>

#define BB 128
#define SS 2048
#define TTAGS 64

__device__ float g_score[BB];
__device__ float g_qmT[TTAGS][BB];   // forward q_{1024}, state-major
__device__ float g_vmT[TTAGS][BB];   // backward v_{1024}, state-major
__device__ int g_esf[BB];
__device__ int g_esb[BB];

// 0 -> 1-byte mask elements (uint8/bool), 1 -> 4-byte (int32/float32).
__device__ __forceinline__ int mask_mode_of(const void* m)
{
    uint32_t w0 = *(const uint32_t*)m;
    if (w0 == 0x01010101u) return 0;
    if (w0 == 0x3F800000u) return 1;
    if ((w0 >> 8) == 0u)   return 1;
    return 0;
}

#define PART_BAR() asm volatile("bar.sync 0;" ::: "memory")

// ---------------------------------------------------------------------------
// Grid = 384 blocks x 160 threads:
//   blocks   0..127 : gold-path score for batch bid           (fast, first)
//   blocks 128..255 : FORWARD half-chain, steps t=1..1024 -> q_{1024}
//   blocks 256..383 : BACKWARD half-chain, rounds t=2047..1025 -> v_{1024}
// Z_b = log(sum_j q_{1024}[j] * v_{1024}[j]) + (esum_f+esum_b)*ln2.
// Both part roles: warps 0-3 consumers (split-K x2: lane pair (l,l+16) owns
// state s = w*16+(l&15); half h = l>>4 does a 32-term half-dot, combined via
// shfl_xor 16), warp 4 producer streaming F_t = exp(em_t + c) into a 16-deep
// shared ring 15 rounds ahead. One bar.sync 0 (160 threads) per step.
// Exact pow2 renorm every 4 steps via exponent of vec[0].
// Backward recurrence: v_{t-1} = m_t ? E_hat . (F_t o v_t) : v_t, where
// E_hat[i,j] = exp(T[i,j]-c_j) and F_t[j] = exp(em_t[j]+c_j)  (exact).
// Shared u = F o v; u_2047 = exp(em_2047 + c + end); final round (t=1025)
// emits v_{1024} without the F multiply.
// ---------------------------------------------------------------------------
__global__ void __launch_bounds__(160, 2) crf_part_score_kernel(
    const float* __restrict__ em,
    const int* __restrict__ tags,
    const void* __restrict__ maskv,
    const float* __restrict__ trans,
    const float* __restrict__ startt,
    const float* __restrict__ endt)
{
    const int t = threadIdx.x;
    const int mmode = mask_mode_of(maskv);

    // ================= score blocks (0..127) =================
    if (blockIdx.x < BB) {
        if (t >= 32) return;
        const int b = blockIdx.x;
        const int lane = t;
        const int* tg = tags + (size_t)b * SS;
        const float* emb = em + (size_t)b * SS * TTAGS;
        const unsigned char* mb8 = (const unsigned char*)maskv + (size_t)b * SS;
        const uint32_t* mb32 = (const uint32_t*)maskv + (size_t)b * SS;

        float s = 0.f;
        int cnt = 0;
        for (int i = lane; i < SS; i += 32) {
            int tc = tg[i];
            int m = (mmode == 0) ? (mb8[i] != 0) : (mb32[i] != 0u);
            cnt += m;
            if (i == 0) {
                s += startt[tc] + emb[tc];
            } else if (m) {
                s += trans[tc * TTAGS + tg[i - 1]] + emb[(size_t)i * TTAGS + tc];
            }
        }
        #pragma unroll
        for (int o = 16; o > 0; o >>= 1) {
            s += __shfl_xor_sync(0xffffffffu, s, o);
            cnt += __shfl_xor_sync(0xffffffffu, cnt, o);
        }
        if (lane == 0) {
            int last = cnt > 0 ? cnt - 1 : 0;
            g_score[b] = s + endt[tg[last]];
        }
        return;
    }

    // ================= partition blocks =================
    __shared__ __align__(16) float qs0[68];
    __shared__ __align__(16) float qs1[68];
    __shared__ __align__(16) float ringF[16][TTAGS];
    __shared__ float csh[TTAGS];
    __shared__ unsigned char msk[SS];

    const int isBwd = (blockIdx.x >= 2 * BB) ? 1 : 0;
    const int b = blockIdx.x - BB - (isBwd ? BB : 0);

    // ---------------- producer warp (threads 128..159) ----------------
    if (t >= 128) {
        const int p = t - 128;
        const int j0 = 2 * p;

        float c0 = -3.0e38f, c1 = -3.0e38f;
        #pragma unroll
        for (int i = 0; i < TTAGS; i++) {
            c0 = fmaxf(c0, trans[i * TTAGS + j0]);
            c1 = fmaxf(c1, trans[i * TTAGS + j0 + 1]);
        }
        const float2* embp =
            (const float2*)(em + (size_t)b * SS * TTAGS + j0);

#define P_LD8(BUF, I0, STEPDIR)                                                 \
        do {                                                                    \
            _Pragma("unroll")                                                   \
            for (int g = 0; g < 8; g++)                                         \
                BUF[g] = embp[(size_t)((I0) + (STEPDIR) * g) * (TTAGS / 2)];    \
        } while (0)

        float2 rA[8], rB[8];

        if (!isBwd) {
            // ---- forward producer: F(1..15) prefill, then F(rt+15) ----
            #pragma unroll
            for (int u = 1; u < 16; u++) {
                float2 r = embp[(size_t)u * (TTAGS / 2)];
                *(float2*)&ringF[u][j0] =
                    make_float2(__expf(r.x + c0), __expf(r.y + c1));
            }
            P_LD8(rA, 16, 1);
            P_LD8(rB, 24, 1);
            PART_BAR();          // init barrier
            #pragma unroll 1
            for (int it = 0; it < 64; it++) {
                const int pbase = 16 + it * 16;
                #pragma unroll
                for (int g = 0; g < 8; g++) {
                    *(float2*)&ringF[g][j0] =
                        make_float2(__expf(rA[g].x + c0), __expf(rA[g].y + c1));
                    PART_BAR();
                }
                P_LD8(rA, pbase + 16, 1);
                #pragma unroll
                for (int g = 0; g < 8; g++) {
                    *(float2*)&ringF[8 + g][j0] =
                        make_float2(__expf(rB[g].x + c0), __expf(rB[g].y + c1));
                    PART_BAR();
                }
                P_LD8(rB, pbase + 24, 1);
            }
            return;
        }

        // ---- backward producer: prefill F(2046..2032) slots 0..14;
        //      at round k produce F(2031-k) into slot (k+15)&15, k<=1006 ----
        #pragma unroll
        for (int s = 0; s < 15; s++) {
            float2 r = embp[(size_t)(2046 - s) * (TTAGS / 2)];
            *(float2*)&ringF[s][j0] =
                make_float2(__expf(r.x + c0), __expf(r.y + c1));
        }
        P_LD8(rA, 2031, -1);     // k = 0..7  -> F_{2031-k}
        P_LD8(rB, 2023, -1);     // k = 8..15 -> F_{2023-g}
        PART_BAR();              // bar A (consumers: csh ready)
        PART_BAR();              // bar B (init)
        #pragma unroll 1
        for (int it = 0; it < 63; it++) {
            const int K0 = it * 16;
            #pragma unroll
            for (int g = 0; g < 8; g++) {
                if (K0 + g <= 1006)
                    *(float2*)&ringF[(g + 15) & 15][j0] =
                        make_float2(__expf(rA[g].x + c0), __expf(rA[g].y + c1));
                PART_BAR();
            }
            P_LD8(rA, 2031 - K0 - 16, -1);
            #pragma unroll
            for (int g = 0; g < 8; g++) {
                if (K0 + 8 + g <= 1006)
                    *(float2*)&ringF[(g + 7) & 15][j0] =
                        make_float2(__expf(rB[g].x + c0), __expf(rB[g].y + c1));
                PART_BAR();
            }
            P_LD8(rB, 2031 - K0 - 24, -1);
        }
        #pragma unroll
        for (int g = 0; g < 15; g++) PART_BAR();   // tail rounds 1008..1022
        return;
#undef P_LD8
    }

    // ---------------- consumer warps (threads 0..127) ----------------
    const int w = t >> 5;
    const int l = t & 31;
    const int st = w * 16 + (l & 15);       // owned state
    const int h = l >> 4;                   // dot half
    const int sidx = st + ((st >> 5) << 2); // padded shared index
    const uint32_t hoff = (uint32_t)h * 144;

    // stage mask
    if (mmode == 0) {
        const uint32_t* m32 =
            (const uint32_t*)((const unsigned char*)maskv + (size_t)b * SS);
        uint32_t* s32 = (uint32_t*)msk;
        #pragma unroll
        for (int i = 0; i < (SS / 4) / 128; i++)
            s32[t + i * 128] = m32[t + i * 128];
    } else {
        const uint32_t* m32 = (const uint32_t*)maskv + (size_t)b * SS;
        #pragma unroll
        for (int i = 0; i < SS / 128; i++)
            msk[t + i * 128] = (m32[t + i * 128] != 0u) ? 1 : 0;
    }

    int esum = 0;
    unsigned long long epk[16];

    // shared accumulator-dot body (identical for both directions)
#define DOT_BODY(SRC)                                                            \
        const ulonglong2* qv =                                                   \
            (const ulonglong2*)((const char*)(SRC) + hoff);                      \
        unsigned long long a0 = 0ull, a1 = 0ull, a2 = 0ull, a3 = 0ull;           \
        _Pragma("unroll")                                                        \
        for (int k2 = 0; k2 < 4; k2++) {                                         \
            ulonglong2 v0 = qv[2 * k2];                                          \
            ulonglong2 v1 = qv[2 * k2 + 1];                                      \
            asm("fma.rn.f32x2 %0, %1, %2, %0;" : "+l"(a0) : "l"(v0.x), "l"(epk[4*k2+0])); \
            asm("fma.rn.f32x2 %0, %1, %2, %0;" : "+l"(a1) : "l"(v0.y), "l"(epk[4*k2+1])); \
            asm("fma.rn.f32x2 %0, %1, %2, %0;" : "+l"(a2) : "l"(v1.x), "l"(epk[4*k2+2])); \
            asm("fma.rn.f32x2 %0, %1, %2, %0;" : "+l"(a3) : "l"(v1.y), "l"(epk[4*k2+3])); \
        }                                                                        \
        asm("add.rn.f32x2 %0, %0, %1;" : "+l"(a0) : "l"(a1));                    \
        asm("add.rn.f32x2 %0, %0, %1;" : "+l"(a2) : "l"(a3));                    \
        asm("add.rn.f32x2 %0, %0, %1;" : "+l"(a0) : "l"(a2));                    \
        float accf = __uint_as_float((uint32_t)a0) +                             \
                     __uint_as_float((uint32_t)(a0 >> 32));                      \
        float tot = accf + __shfl_xor_sync(0xffffffffu, accf, 16);

    if (!isBwd) {
        // ======== FORWARD consumers ========
        float c = -3.0e38f;
        #pragma unroll
        for (int i = 0; i < TTAGS; i++) c = fmaxf(c, trans[i * TTAGS + st]);
        #pragma unroll
        for (int k = 0; k < 16; k++) {
            int i0 = h * 32 + 2 * k;
            float e0 = __expf(trans[i0 * TTAGS + st] - c);
            float e1 = __expf(trans[(i0 + 1) * TTAGS + st] - c);
            epk[k] = (unsigned long long)__float_as_uint(e0) |
                     ((unsigned long long)__float_as_uint(e1) << 32);
        }
        float qreg = __expf(startt[st] + em[(size_t)b * SS * TTAGS + st]);
        if (h == 0) qs0[sidx] = qreg;
        PART_BAR();

#define FWD_STEP(QSRC, QDST, TTI, SL, DOREN)                                     \
        do {                                                                     \
            int mv = msk[(TTI)];                                                 \
            float Fv = ringF[(SL)][st];                                          \
            uint32_t q0w = 0;                                                    \
            if (DOREN) q0w = *(const uint32_t*)(QSRC);                           \
            DOT_BODY(QSRC)                                                       \
            float tj = tot * Fv;                                                 \
            float qn = mv ? tj : qreg;                                           \
            if (DOREN) {                                                         \
                int e = (int)((q0w >> 23) & 0xffu) - 127;                        \
                qn *= __int_as_float((127 - e) << 23);                           \
                esum += e;                                                       \
            }                                                                    \
            qreg = qn;                                                           \
            if (h == 0) (QDST)[sidx] = qn;                                       \
            PART_BAR();                                                          \
        } while (0)

        #pragma unroll 1
        for (int it = 0; it < 64; it++) {
            const int base = 1 + it * 16;
            #pragma unroll
            for (int gg = 0; gg < 16; gg += 2) {
                FWD_STEP(qs0, qs1, base + gg, (1 + gg) & 15, ((gg & 3) == 0));
                FWD_STEP(qs1, qs0, base + gg + 1, (2 + gg) & 15, 0);
            }
        }
        if (h == 0) g_qmT[st][b] = qreg;
        if (t == 0) g_esf[b] = esum;
        return;
#undef FWD_STEP
    }

    // ======== BACKWARD consumers ========
    // cooperative column maxes
    if (t < TTAGS) {
        float cm = -3.0e38f;
        #pragma unroll
        for (int i = 0; i < TTAGS; i++) cm = fmaxf(cm, trans[i * TTAGS + t]);
        csh[t] = cm;
    }
    PART_BAR();   // bar A

    // row-based Ehat: epk[k] = (exp(T[st][j0]-c_{j0}), exp(T[st][j0+1]-c_{j0+1}))
    #pragma unroll
    for (int k = 0; k < 16; k++) {
        int j0 = h * 32 + 2 * k;
        float e0 = __expf(trans[st * TTAGS + j0] - csh[j0]);
        float e1 = __expf(trans[st * TTAGS + j0 + 1] - csh[j0 + 1]);
        epk[k] = (unsigned long long)__float_as_uint(e0) |
                 ((unsigned long long)__float_as_uint(e1) << 32);
    }
    float vv = __expf(endt[st]);
    if (h == 0)
        qs0[sidx] = __expf(em[(size_t)b * SS * TTAGS + 2047 * TTAGS + st] +
                           csh[st] + endt[st]);   // u_2047 = F_2047 * v_2047
    PART_BAR();   // bar B (init)

#define BWD_STEP(USRC, UDST, TTI, SL, DOREN)                                     \
    do {                                                                         \
        int mv = msk[(TTI)];                                                     \
        float Fv = ringF[(SL)][st];                                              \
        uint32_t u0w = 0;                                                        \
        if (DOREN) u0w = *(const uint32_t*)(USRC);                               \
        DOT_BODY(USRC)                                                           \
        float vn = mv ? tot : vv;                                                \
        if (DOREN) {                                                             \
            int e = (int)((u0w >> 23) & 0xffu) - 127;                            \
            vn *= __int_as_float((127 - e) << 23);                               \
            esum += e;                                                           \
        }                                                                        \
        vv = vn;                                                                 \
        if (h == 0) (UDST)[sidx] = vn * Fv;                                      \
        PART_BAR();                                                              \
    } while (0)

    // main rounds k = 0..1007 (t = 2047 down to 1040)
    #pragma unroll 1
    for (int it = 0; it < 63; it++) {
        const int ttb = 2047 - it * 16;
        #pragma unroll
        for (int g = 0; g < 16; g += 2) {
            BWD_STEP(qs0, qs1, ttb - g, (g) & 15, ((g & 3) == 0));
            BWD_STEP(qs1, qs0, ttb - g - 1, (g + 1) & 15, 0);
        }
    }
    // tail rounds k = 1008..1021 (t = 1039..1026)
    #pragma unroll
    for (int g = 0; g < 14; g += 2) {
        BWD_STEP(qs0, qs1, 1039 - g, (g) & 15, ((g & 3) == 0));
        BWD_STEP(qs1, qs0, 1038 - g, (g + 1) & 15, 0);
    }
    // final round k = 1022 (t = 1025): v_{1024} = m ? E.u_{1025} : v_{1025}
    {
        int mv = msk[1025];
        DOT_BODY(qs0)
        float vn = mv ? tot : vv;
        PART_BAR();
        if (h == 0) g_vmT[st][b] = vn;
        if (t == 0) g_esb[b] = esum;
    }
#undef BWD_STEP
#undef DOT_BODY
}

// ---------------------------------------------------------------------------
// out = mean( log(q.v) + (esf+esb)ln2  -  score )
// ---------------------------------------------------------------------------
__global__ void crf_final_kernel(float* __restrict__ out)
{
    const int i = threadIdx.x;  // 128 threads = one batch each
    double acc = 0.0;
    #pragma unroll
    for (int k = 0; k < TTAGS; k++)
        acc += (double)g_qmT[k][i] * (double)g_vmT[k][i];
    double Z = log(acc) +
               (double)(g_esf[i] + g_esb[i]) * 0.6931471805599453;
    double v = Z - (double)g_score[i];
    #pragma unroll
    for (int o = 16; o > 0; o >>= 1)
        v += __shfl_xor_sync(0xffffffffu, v, o);
    __shared__ double sm[4];
    if ((i & 31) == 0) sm[i >> 5] = v;
    __syncthreads();
    if (i == 0)
        out[0] = (float)((sm[0] + sm[1] + sm[2] + sm[3]) * (1.0 / (double)BB));
}

extern "C" void kernel_launch(void* const* d_in, const int* in_sizes, int n_in,
                              void* d_out, int out_size)
{
    const float* em     = (const float*)d_in[0];
    const int* tags     = (const int*)d_in[1];
    const void* mask    = (const void*)d_in[2];
    const float* trans  = (const float*)d_in[3];
    const float* startt = (const float*)d_in[4];
    const float* endt   = (const float*)d_in[5];

    crf_part_score_kernel<<<3 * BB, 160>>>(em, tags, mask, trans, startt, endt);
    crf_final_kernel<<<1, 128>>>((float*)d_out);
}

// round 17
// speedup vs baseline: 1.4595x; 1.0894x over previous
#include <cuda_runtime.h>
#include <cstdint>
#include <math.h>

#define BB 128
#define SS 2048
#define TTAGS 64

__device__ float g_score[BB];
__device__ float g_qmT[TTAGS][BB];   // forward q_{1024}, state-major
__device__ float g_vmT[TTAGS][BB];   // backward v_{1024}, state-major
__device__ int g_esf[BB];
__device__ int g_esb[BB];

// 0 -> 1-byte mask elements (uint8/bool), 1 -> 4-byte (int32/float32).
__device__ __forceinline__ int mask_mode_of(const void* m)
{
    uint32_t w0 = *(const uint32_t*)m;
    if (w0 == 0x01010101u) return 0;
    if (w0 == 0x3F800000u) return 1;
    if ((w0 >> 8) == 0u)   return 1;
    return 0;
}

#define PART_BAR() asm volatile("bar.sync 0;" ::: "memory")

// ---------------------------------------------------------------------------
// Grid = 384 blocks x 160 threads:
//   blocks   0..127 : FORWARD half-chain, steps t=1..1024 -> q_{1024}
//   blocks 128..255 : BACKWARD half-chain, rounds t=2047..1025 -> v_{1024}
//   blocks 256..383 : gold-path score (placed LAST: all 256 part blocks start
//                     in wave 1 at occ=2; score backfills spare/freed slots)
// Z_b = log(sum_j q_{1024}[j] * v_{1024}[j]) + (esum_f+esum_b)*ln2.
// Part roles: warps 0-3 consumers (split-K x2: lane pair (l,l+16) owns state
// s = w*16+(l&15); half h = l>>4 does a 32-term half-dot, combined via
// shfl_xor 16), warp 4 producer streaming F_t = exp(em_t + c) into a 16-deep
// shared ring 15 rounds ahead. One bar.sync 0 (160 threads) per step.
// Exact pow2 renorm every 4 steps via exponent of vec[0].
// Backward recurrence: v_{t-1} = m_t ? E_hat . (F_t o v_t) : v_t, where
// E_hat[i,j] = exp(T[i,j]-c_j) and F_t[j] = exp(em_t[j]+c_j)  (exact).
// Shared u = F o v; u_2047 = exp(em_2047 + c + end); final round (t=1025)
// emits v_{1024} without the F multiply.
// ---------------------------------------------------------------------------
__global__ void __launch_bounds__(160, 2) crf_part_score_kernel(
    const float* __restrict__ em,
    const int* __restrict__ tags,
    const void* __restrict__ maskv,
    const float* __restrict__ trans,
    const float* __restrict__ startt,
    const float* __restrict__ endt)
{
    const int t = threadIdx.x;
    const int mmode = mask_mode_of(maskv);

    // ================= score blocks (256..383) =================
    if (blockIdx.x >= 2 * BB) {
        if (t >= 32) return;
        const int b = blockIdx.x - 2 * BB;
        const int lane = t;
        const int* tg = tags + (size_t)b * SS;
        const float* emb = em + (size_t)b * SS * TTAGS;
        const unsigned char* mb8 = (const unsigned char*)maskv + (size_t)b * SS;
        const uint32_t* mb32 = (const uint32_t*)maskv + (size_t)b * SS;

        float s = 0.f;
        int cnt = 0;
        for (int i = lane; i < SS; i += 32) {
            int tc = tg[i];
            int m = (mmode == 0) ? (mb8[i] != 0) : (mb32[i] != 0u);
            cnt += m;
            if (i == 0) {
                s += startt[tc] + emb[tc];
            } else if (m) {
                s += trans[tc * TTAGS + tg[i - 1]] + emb[(size_t)i * TTAGS + tc];
            }
        }
        #pragma unroll
        for (int o = 16; o > 0; o >>= 1) {
            s += __shfl_xor_sync(0xffffffffu, s, o);
            cnt += __shfl_xor_sync(0xffffffffu, cnt, o);
        }
        if (lane == 0) {
            int last = cnt > 0 ? cnt - 1 : 0;
            g_score[b] = s + endt[tg[last]];
        }
        return;
    }

    // ================= partition blocks (0..255) =================
    __shared__ __align__(16) float qs0[68];
    __shared__ __align__(16) float qs1[68];
    __shared__ __align__(16) float ringF[16][TTAGS];
    __shared__ float csh[TTAGS];
    __shared__ unsigned char msk[SS];

    const int isBwd = (blockIdx.x >= BB) ? 1 : 0;
    const int b = blockIdx.x - (isBwd ? BB : 0);

    // ---------------- producer warp (threads 128..159) ----------------
    if (t >= 128) {
        const int p = t - 128;
        const int j0 = 2 * p;

        float c0 = -3.0e38f, c1 = -3.0e38f;
        #pragma unroll
        for (int i = 0; i < TTAGS; i++) {
            c0 = fmaxf(c0, trans[i * TTAGS + j0]);
            c1 = fmaxf(c1, trans[i * TTAGS + j0 + 1]);
        }
        const float2* embp =
            (const float2*)(em + (size_t)b * SS * TTAGS + j0);

#define P_LD8(BUF, I0, STEPDIR)                                                 \
        do {                                                                    \
            _Pragma("unroll")                                                   \
            for (int g = 0; g < 8; g++)                                         \
                BUF[g] = embp[(size_t)((I0) + (STEPDIR) * g) * (TTAGS / 2)];    \
        } while (0)

        float2 rA[8], rB[8];

        if (!isBwd) {
            // ---- forward producer: F(1..15) prefill, then F(rt+15) ----
            #pragma unroll
            for (int u = 1; u < 16; u++) {
                float2 r = embp[(size_t)u * (TTAGS / 2)];
                *(float2*)&ringF[u][j0] =
                    make_float2(__expf(r.x + c0), __expf(r.y + c1));
            }
            P_LD8(rA, 16, 1);
            P_LD8(rB, 24, 1);
            PART_BAR();          // init barrier
            #pragma unroll 1
            for (int it = 0; it < 64; it++) {
                const int pbase = 16 + it * 16;
                #pragma unroll
                for (int g = 0; g < 8; g++) {
                    *(float2*)&ringF[g][j0] =
                        make_float2(__expf(rA[g].x + c0), __expf(rA[g].y + c1));
                    PART_BAR();
                }
                P_LD8(rA, pbase + 16, 1);
                #pragma unroll
                for (int g = 0; g < 8; g++) {
                    *(float2*)&ringF[8 + g][j0] =
                        make_float2(__expf(rB[g].x + c0), __expf(rB[g].y + c1));
                    PART_BAR();
                }
                P_LD8(rB, pbase + 24, 1);
            }
            return;
        }

        // ---- backward producer: prefill F(2046..2032) slots 0..14;
        //      at round k produce F(2031-k) into slot (k+15)&15, k<=1006 ----
        #pragma unroll
        for (int s = 0; s < 15; s++) {
            float2 r = embp[(size_t)(2046 - s) * (TTAGS / 2)];
            *(float2*)&ringF[s][j0] =
                make_float2(__expf(r.x + c0), __expf(r.y + c1));
        }
        P_LD8(rA, 2031, -1);     // k = 0..7  -> F_{2031-k}
        P_LD8(rB, 2023, -1);     // k = 8..15 -> F_{2023-g}
        PART_BAR();              // bar A (consumers: csh ready)
        PART_BAR();              // bar B (init)
        #pragma unroll 1
        for (int it = 0; it < 63; it++) {
            const int K0 = it * 16;
            #pragma unroll
            for (int g = 0; g < 8; g++) {
                if (K0 + g <= 1006)
                    *(float2*)&ringF[(g + 15) & 15][j0] =
                        make_float2(__expf(rA[g].x + c0), __expf(rA[g].y + c1));
                PART_BAR();
            }
            P_LD8(rA, 2031 - K0 - 16, -1);
            #pragma unroll
            for (int g = 0; g < 8; g++) {
                if (K0 + 8 + g <= 1006)
                    *(float2*)&ringF[(g + 7) & 15][j0] =
                        make_float2(__expf(rB[g].x + c0), __expf(rB[g].y + c1));
                PART_BAR();
            }
            P_LD8(rB, 2031 - K0 - 24, -1);
        }
        #pragma unroll
        for (int g = 0; g < 15; g++) PART_BAR();   // tail rounds 1008..1022
        return;
#undef P_LD8
    }

    // ---------------- consumer warps (threads 0..127) ----------------
    const int w = t >> 5;
    const int l = t & 31;
    const int st = w * 16 + (l & 15);       // owned state
    const int h = l >> 4;                   // dot half
    const int sidx = st + ((st >> 5) << 2); // padded shared index
    const uint32_t hoff = (uint32_t)h * 144;

    // stage mask
    if (mmode == 0) {
        const uint32_t* m32 =
            (const uint32_t*)((const unsigned char*)maskv + (size_t)b * SS);
        uint32_t* s32 = (uint32_t*)msk;
        #pragma unroll
        for (int i = 0; i < (SS / 4) / 128; i++)
            s32[t + i * 128] = m32[t + i * 128];
    } else {
        const uint32_t* m32 = (const uint32_t*)maskv + (size_t)b * SS;
        #pragma unroll
        for (int i = 0; i < SS / 128; i++)
            msk[t + i * 128] = (m32[t + i * 128] != 0u) ? 1 : 0;
    }

    int esum = 0;
    unsigned long long epk[16];

    // shared accumulator-dot body (identical for both directions)
#define DOT_BODY(SRC)                                                            \
        const ulonglong2* qv =                                                   \
            (const ulonglong2*)((const char*)(SRC) + hoff);                      \
        unsigned long long a0 = 0ull, a1 = 0ull, a2 = 0ull, a3 = 0ull;           \
        _Pragma("unroll")                                                        \
        for (int k2 = 0; k2 < 4; k2++) {                                         \
            ulonglong2 v0 = qv[2 * k2];                                          \
            ulonglong2 v1 = qv[2 * k2 + 1];                                      \
            asm("fma.rn.f32x2 %0, %1, %2, %0;" : "+l"(a0) : "l"(v0.x), "l"(epk[4*k2+0])); \
            asm("fma.rn.f32x2 %0, %1, %2, %0;" : "+l"(a1) : "l"(v0.y), "l"(epk[4*k2+1])); \
            asm("fma.rn.f32x2 %0, %1, %2, %0;" : "+l"(a2) : "l"(v1.x), "l"(epk[4*k2+2])); \
            asm("fma.rn.f32x2 %0, %1, %2, %0;" : "+l"(a3) : "l"(v1.y), "l"(epk[4*k2+3])); \
        }                                                                        \
        asm("add.rn.f32x2 %0, %0, %1;" : "+l"(a0) : "l"(a1));                    \
        asm("add.rn.f32x2 %0, %0, %1;" : "+l"(a2) : "l"(a3));                    \
        asm("add.rn.f32x2 %0, %0, %1;" : "+l"(a0) : "l"(a2));                    \
        float accf = __uint_as_float((uint32_t)a0) +                             \
                     __uint_as_float((uint32_t)(a0 >> 32));                      \
        float tot = accf + __shfl_xor_sync(0xffffffffu, accf, 16);

    if (!isBwd) {
        // ======== FORWARD consumers ========
        float c = -3.0e38f;
        #pragma unroll
        for (int i = 0; i < TTAGS; i++) c = fmaxf(c, trans[i * TTAGS + st]);
        #pragma unroll
        for (int k = 0; k < 16; k++) {
            int i0 = h * 32 + 2 * k;
            float e0 = __expf(trans[i0 * TTAGS + st] - c);
            float e1 = __expf(trans[(i0 + 1) * TTAGS + st] - c);
            epk[k] = (unsigned long long)__float_as_uint(e0) |
                     ((unsigned long long)__float_as_uint(e1) << 32);
        }
        float qreg = __expf(startt[st] + em[(size_t)b * SS * TTAGS + st]);
        if (h == 0) qs0[sidx] = qreg;
        PART_BAR();

#define FWD_STEP(QSRC, QDST, TTI, SL, DOREN)                                     \
        do {                                                                     \
            int mv = msk[(TTI)];                                                 \
            float Fv = ringF[(SL)][st];                                          \
            uint32_t q0w = 0;                                                    \
            if (DOREN) q0w = *(const uint32_t*)(QSRC);                           \
            DOT_BODY(QSRC)                                                       \
            float tj = tot * Fv;                                                 \
            float qn = mv ? tj : qreg;                                           \
            if (DOREN) {                                                         \
                int e = (int)((q0w >> 23) & 0xffu) - 127;                        \
                qn *= __int_as_float((127 - e) << 23);                           \
                esum += e;                                                       \
            }                                                                    \
            qreg = qn;                                                           \
            if (h == 0) (QDST)[sidx] = qn;                                       \
            PART_BAR();                                                          \
        } while (0)

        #pragma unroll 1
        for (int it = 0; it < 64; it++) {
            const int base = 1 + it * 16;
            #pragma unroll
            for (int gg = 0; gg < 16; gg += 2) {
                FWD_STEP(qs0, qs1, base + gg, (1 + gg) & 15, ((gg & 3) == 0));
                FWD_STEP(qs1, qs0, base + gg + 1, (2 + gg) & 15, 0);
            }
        }
        if (h == 0) g_qmT[st][b] = qreg;
        if (t == 0) g_esf[b] = esum;
        return;
#undef FWD_STEP
    }

    // ======== BACKWARD consumers ========
    // cooperative column maxes
    if (t < TTAGS) {
        float cm = -3.0e38f;
        #pragma unroll
        for (int i = 0; i < TTAGS; i++) cm = fmaxf(cm, trans[i * TTAGS + t]);
        csh[t] = cm;
    }
    PART_BAR();   // bar A

    // row-based Ehat: epk[k] = (exp(T[st][j0]-c_{j0}), exp(T[st][j0+1]-c_{j0+1}))
    #pragma unroll
    for (int k = 0; k < 16; k++) {
        int j0 = h * 32 + 2 * k;
        float e0 = __expf(trans[st * TTAGS + j0] - csh[j0]);
        float e1 = __expf(trans[st * TTAGS + j0 + 1] - csh[j0 + 1]);
        epk[k] = (unsigned long long)__float_as_uint(e0) |
                 ((unsigned long long)__float_as_uint(e1) << 32);
    }
    float vv = __expf(endt[st]);
    if (h == 0)
        qs0[sidx] = __expf(em[(size_t)b * SS * TTAGS + 2047 * TTAGS + st] +
                           csh[st] + endt[st]);   // u_2047 = F_2047 * v_2047
    PART_BAR();   // bar B (init)

#define BWD_STEP(USRC, UDST, TTI, SL, DOREN)                                     \
    do {                                                                         \
        int mv = msk[(TTI)];                                                     \
        float Fv = ringF[(SL)][st];                                              \
        uint32_t u0w = 0;                                                        \
        if (DOREN) u0w = *(const uint32_t*)(USRC);                               \
        DOT_BODY(USRC)                                                           \
        float vn = mv ? tot : vv;                                                \
        if (DOREN) {                                                             \
            int e = (int)((u0w >> 23) & 0xffu) - 127;                            \
            vn *= __int_as_float((127 - e) << 23);                               \
            esum += e;                                                           \
        }                                                                        \
        vv = vn;                                                                 \
        if (h == 0) (UDST)[sidx] = vn * Fv;                                      \
        PART_BAR();                                                              \
    } while (0)

    // main rounds k = 0..1007 (t = 2047 down to 1040)
    #pragma unroll 1
    for (int it = 0; it < 63; it++) {
        const int ttb = 2047 - it * 16;
        #pragma unroll
        for (int g = 0; g < 16; g += 2) {
            BWD_STEP(qs0, qs1, ttb - g, (g) & 15, ((g & 3) == 0));
            BWD_STEP(qs1, qs0, ttb - g - 1, (g + 1) & 15, 0);
        }
    }
    // tail rounds k = 1008..1021 (t = 1039..1026)
    #pragma unroll
    for (int g = 0; g < 14; g += 2) {
        BWD_STEP(qs0, qs1, 1039 - g, (g) & 15, ((g & 3) == 0));
        BWD_STEP(qs1, qs0, 1038 - g, (g + 1) & 15, 0);
    }
    // final round k = 1022 (t = 1025): v_{1024} = m ? E.u_{1025} : v_{1025}
    {
        int mv = msk[1025];
        DOT_BODY(qs0)
        float vn = mv ? tot : vv;
        PART_BAR();
        if (h == 0) g_vmT[st][b] = vn;
        if (t == 0) g_esb[b] = esum;
    }
#undef BWD_STEP
#undef DOT_BODY
}

// ---------------------------------------------------------------------------
// out = mean( log(q.v) + (esf+esb)ln2  -  score )   (fp32 hot path)
// ---------------------------------------------------------------------------
__global__ void crf_final_kernel(float* __restrict__ out)
{
    const int i = threadIdx.x;  // 128 threads = one batch each
    float acc = 0.f;
    #pragma unroll
    for (int k = 0; k < TTAGS; k++)
        acc = fmaf(g_qmT[k][i], g_vmT[k][i], acc);
    float Z = logf(acc) +
              (float)(g_esf[i] + g_esb[i]) * 0.69314718055994530942f;
    double v = (double)Z - (double)g_score[i];
    #pragma unroll
    for (int o = 16; o > 0; o >>= 1)
        v += __shfl_xor_sync(0xffffffffu, v, o);
    __shared__ double sm[4];
    if ((i & 31) == 0) sm[i >> 5] = v;
    __syncthreads();
    if (i == 0)
        out[0] = (float)((sm[0] + sm[1] + sm[2] + sm[3]) * (1.0 / (double)BB));
}

extern "C" void kernel_launch(void* const* d_in, const int* in_sizes, int n_in,
                              void* d_out, int out_size)
{
    const float* em     = (const float*)d_in[0];
    const int* tags     = (const int*)d_in[1];
    const void* mask    = (const void*)d_in[2];
    const float* trans  = (const float*)d_in[3];
    const float* startt = (const float*)d_in[4];
    const float* endt   = (const float*)d_in[5];

    crf_part_score_kernel<<<3 * BB, 160>>>(em, tags, mask, trans, startt, endt);
    crf_final_kernel<<<1, 128>>>((float*)d_out);
}